// round 14
// baseline (speedup 1.0000x reference)
#include <cuda_runtime.h>
#include <cuda_bf16.h>
#include <math.h>

#define N384 384
#define NPIX (384*384)
#define HALF_PIX (193*384)
#define PI_F 3.14159265358979323846f

// -------- scratch (static __device__ arrays; allocation is forbidden) --------
__device__ float2 g_A  [12*NPIX];
__device__ float2 g_Xs [12*NPIX];
__device__ float2 g_Att[ 4*NPIX];
__device__ float2 g_Tmp[36*NPIX];
__device__ float  g_Cv [12*NPIX];

__device__ __forceinline__ float2 cmul(float2 a, float2 b) {
    return make_float2(a.x*b.x - a.y*b.y, a.x*b.y + a.y*b.x);
}

// ---- 384-pt Stockham FFT, stages 1..4 (radix-3 + 3x radix-4) ----------------
// Input in s0. After return: pre-final data in s0 (synced). The final radix-2
// stage (twiddle=1) is butterfly  out[q]=u+v, out[q+192]=u-v  with
// u=s0[c*384+q], v=s0[c*384+q+192]; callers fuse it into their epilogue.
template<int NC>
__device__ void fft384_pre(float2* s0, float2* s1, int tid, int nt, float dir)
{
    __syncthreads();
    {
        const float th0 = dir * (2.0f * PI_F / 384.0f);
        const float s3  = dir * 0.8660254037844386f;
        const int total = NC * 128;
        for (int idx = tid; idx < total; idx += nt) {
            int c = idx >> 7;
            int p = idx & 127;
            const float2* x = s0 + c*N384;
            float2*       y = s1 + c*N384;
            float2 a = x[p], b = x[p+128], cc = x[p+256];
            float t1x = b.x+cc.x, t1y = b.y+cc.y;
            float t2x = b.x-cc.x, t2y = b.y-cc.y;
            float2 x0 = make_float2(a.x+t1x, a.y+t1y);
            float ux = a.x - 0.5f*t1x, uy = a.y - 0.5f*t1y;
            float vx = -s3*t2y,        vy =  s3*t2x;
            float2 x1 = make_float2(ux+vx, uy+vy);
            float2 x2 = make_float2(ux-vx, uy-vy);
            float cw, sw; __sincosf(th0 * (float)p, &sw, &cw);
            float2 w1 = make_float2(cw, sw);
            float2 w2 = cmul(w1, w1);
            y[3*p  ] = x0;
            y[3*p+1] = cmul(x1, w1);
            y[3*p+2] = cmul(x2, w2);
        }
        __syncthreads();
    }
    #pragma unroll
    for (int stage = 0; stage < 3; stage++) {
        const int nn = (stage==0) ? 128 : (stage==1) ? 32 : 8;
        const int ss = (stage==0) ?   3 : (stage==1) ? 12 : 48;
        const int n4 = nn >> 2;
        float2* src = (stage==1) ? s0 : s1;
        float2* dst = (stage==1) ? s1 : s0;
        const float th0 = dir * (2.0f * PI_F / (float)nn);
        const int total = NC * 96;
        for (int idx = tid; idx < total; idx += nt) {
            int c = idx / 96;
            int r = idx - c*96;
            int p = r / ss;
            int q = r - p*ss;
            const float2* x = src + c*N384;
            float2*       y = dst + c*N384;
            float2 x0 = x[q + ss*p];
            float2 x1 = x[q + ss*(p +   n4)];
            float2 x2 = x[q + ss*(p + 2*n4)];
            float2 x3 = x[q + ss*(p + 3*n4)];
            float2 e0 = make_float2(x0.x+x2.x, x0.y+x2.y);
            float2 e1 = make_float2(x1.x+x3.x, x1.y+x3.y);
            float2 d0 = make_float2(x0.x-x2.x, x0.y-x2.y);
            float2 d1 = make_float2(x1.x-x3.x, x1.y-x3.y);
            float2 id1 = make_float2(-dir*d1.y, dir*d1.x);
            float2 u0 = make_float2(e0.x+e1.x,  e0.y+e1.y);
            float2 u1 = make_float2(d0.x+id1.x, d0.y+id1.y);
            float2 u2 = make_float2(e0.x-e1.x,  e0.y-e1.y);
            float2 u3 = make_float2(d0.x-id1.x, d0.y-id1.y);
            float cw, sw; __sincosf(th0 * (float)p, &sw, &cw);
            float2 w1 = make_float2(cw, sw);
            float2 w2 = cmul(w1, w1);
            float2 w3 = cmul(w2, w1);
            y[q + ss*(4*p)  ] = u0;
            y[q + ss*(4*p+1)] = cmul(u1, w1);
            y[q + ss*(4*p+2)] = cmul(u2, w2);
            y[q + ss*(4*p+3)] = cmul(u3, w3);
        }
        __syncthreads();
    }
    // data now in s0, synced
}

// full FFT incl. final radix-2: result in s1 (used by k_fwd_row only)
template<int NC>
__device__ void fft384_multi(float2* s0, float2* s1, int tid, int nt, float dir)
{
    fft384_pre<NC>(s0, s1, tid, nt, dir);
    {
        const int total = NC * 192;
        for (int idx = tid; idx < total; idx += nt) {
            int c = idx / 192;
            int q = idx - c*192;
            const float2* x = s0 + c*N384;
            float2*       y = s1 + c*N384;
            float2 a = x[q], b = x[q+192];
            y[q]     = make_float2(a.x+b.x, a.y+b.y);
            y[q+192] = make_float2(a.x-b.x, a.y-b.y);
        }
        __syncthreads();
    }
}

// -------- forward row pass: real-input packing, 8 rows/block -----------------
__global__ void k_fwd_row(const float* __restrict__ x)
{
    __shared__ float2 s0[4*N384], s1[4*N384];
    int img  = blockIdx.x / 48;
    int tile = blockIdx.x - img*48;
    int r0 = tile * 8;
    int b = img / 3, d = img - b*3;
    int bs = (b + 2) & 3;
    int ds = (d + 2) % 3;
    const float* xr = x + ((size_t)(bs*3 + ds)*NPIX) + (size_t)r0*N384;
    for (int idx = threadIdx.x; idx < 4*N384; idx += blockDim.x) {
        int c = idx / N384, w = idx - c*N384;
        s0[idx] = make_float2(xr[(2*c)*N384 + w], xr[(2*c+1)*N384 + w]);
    }
    fft384_multi<4>(s0, s1, threadIdx.x, blockDim.x, -1.f);
    float2* out = g_A + (size_t)img*NPIX + (size_t)r0*N384;
    for (int idx = threadIdx.x; idx < 4*N384; idx += blockDim.x) {
        int c = idx / N384, w = idx - c*N384;
        int mw = (w == 0) ? 0 : (N384 - w);
        float2 F1 = s1[c*N384 + w];
        float2 F2 = s1[c*N384 + mw];
        float2 ev = make_float2(0.5f*(F1.x + F2.x), 0.5f*(F1.y - F2.y));
        float dx = F1.x - F2.x, dy = F1.y + F2.y;
        float2 od = make_float2(0.5f*dy, -0.5f*dx);
        out[(2*c)*N384 + w]   = ev;
        out[(2*c+1)*N384 + w] = od;
    }
}

// -------- forward column pass: Hermitian halving (+h,w shift) ----------------
// Final radix-2 fused into the shifted/mirrored store.
__device__ __forceinline__ void fwdcol_store(float2* Xs, int hh, int l, float2 v)
{
    if (l <= 192) {
        int h2 = hh + 192; if (h2 >= N384) h2 -= N384;
        int w2 = l + 192;  if (w2 >= N384) w2 -= N384;
        Xs[h2*N384 + w2] = v;
    }
    if (l >= 1 && l <= 191) {
        int hm = ((N384 - hh) % N384) + 192; if (hm >= N384) hm -= N384;
        int wm = 192 - l;
        Xs[hm*N384 + wm] = make_float2(v.x, -v.y);
    }
}

__global__ void k_fwd_col()
{
    __shared__ float2 s0[4*N384], s1[4*N384];
    int img  = blockIdx.x / 49;
    int tile = blockIdx.x - img*49;
    int c0 = tile * 4;
    const float2* A = g_A + (size_t)img*NPIX;
    for (int idx = threadIdx.x; idx < 4*N384; idx += blockDim.x) {
        int h = idx >> 2, c = idx & 3;
        s0[c*N384 + h] = A[h*N384 + c0 + c];
    }
    fft384_pre<4>(s0, s1, threadIdx.x, blockDim.x, -1.f);
    float2* Xs = g_Xs + (size_t)img*NPIX;
    for (int idx = threadIdx.x; idx < 4*192; idx += blockDim.x) {
        int c = idx / 192, q = idx - c*192;
        float2 u = s0[c*N384 + q];
        float2 v = s0[c*N384 + q + 192];
        int l = c0 + c;
        fwdcol_store(Xs, q,       l, make_float2(u.x+v.x, u.y+v.y));
        fwdcol_store(Xs, q + 192, l, make_float2(u.x-v.x, u.y-v.y));
    }
}

// --- fused attention: half-plane MLP + softmax + filt(p & mirror) + combine --
__global__ void __launch_bounds__(256)
k_attn(const float* __restrict__ theta, const float* __restrict__ sigma,
       const float* __restrict__ f0,    const float* __restrict__ theta0,
       const float* __restrict__ w1,    const float* __restrict__ b1,
       const float* __restrict__ w2,    const float* __restrict__ b2)
{
    __shared__ float4 sw1v[64];
    __shared__ float4 sw2v[192];
    __shared__ float  sb2[9];
    __shared__ float  sth[27], slf0[27], sc1[27], sc2[27];
    __shared__ int    s_uni;
    int tid = threadIdx.x;
    if (tid < 64)
        sw1v[tid] = make_float4(w1[tid*3], w1[tid*3+1], w1[tid*3+2], b1[tid]);
    for (int i = tid; i < 192; i += 256) {
        int j = i / 3, k = i - 3*j;
        int o0 = k*4;
        sw2v[i] = make_float4(w2[o0*64 + j],
                              (o0+1 < 9) ? w2[(o0+1)*64 + j] : 0.f,
                              (o0+2 < 9) ? w2[(o0+2)*64 + j] : 0.f,
                              (o0+3 < 9) ? w2[(o0+3)*64 + j] : 0.f);
    }
    if (tid < 9) sb2[tid] = b2[tid];
    if (tid < 27) {
        sth[tid]  = theta[tid];
        float ls  = __logf(sigma[tid]);
        sc1[tid]  = -0.5f / (ls*ls);
        float t0  = theta0[tid];
        sc2[tid]  = -0.5f / (t0*t0);
        slf0[tid] = __logf(f0[tid]);
    }
    __syncthreads();
    if (tid == 0) {
        int u = 1;
        #pragma unroll
        for (int i = 1; i < 27; i++) if (slf0[i] != slf0[0]) u = 0;
        s_uni = u;
    }
    __syncthreads();
    const int uni = s_uni;

    int p = blockIdx.x*256 + tid;
    if (p >= HALF_PIX) return;
    int h = p / N384, w = p - h*N384;
    int hm = (N384 - h) % N384;
    int wm = (N384 - w) % N384;
    int pm = hm*N384 + wm;

    float fp[27], fm[27];
    {
        float yy = -1.f + (2.f/383.f) * (float)h;
        float xx = -1.f + (2.f/383.f) * (float)w;
        float r   = sqrtf(xx*xx + yy*yy + 1e-6f);
        float phi = atan2f(yy, xx);
        float ym = -1.f + (2.f/383.f) * (float)hm;
        float xm = -1.f + (2.f/383.f) * (float)wm;
        float rm   = sqrtf(xm*xm + ym*ym + 1e-6f);
        float phim = atan2f(ym, xm);
        if (uni) {
            float lr = __logf(r - slf0[0]);   float lr2 = lr*lr;
            float lm = __logf(rm - slf0[0]);  float lm2 = lm*lm;
            #pragma unroll
            for (int i = 0; i < 27; i++) {
                float dp = phi  - sth[i];
                float dm = phim - sth[i];
                fp[i] = __expf(fmaf(lr2, sc1[i], dp*dp*sc2[i]));
                fm[i] = __expf(fmaf(lm2, sc1[i], dm*dm*sc2[i]));
            }
        } else {
            #pragma unroll
            for (int i = 0; i < 27; i++) {
                float lr = __logf(r  - slf0[i]);
                float lm = __logf(rm - slf0[i]);
                float dp = phi  - sth[i];
                float dm = phim - sth[i];
                fp[i] = __expf(fmaf(lr*lr, sc1[i], dp*dp*sc2[i]));
                fm[i] = __expf(fmaf(lm*lm, sc1[i], dm*dm*sc2[i]));
            }
        }
    }

    #pragma unroll
    for (int b = 0; b < 4; b++) {
        float2 X0 = g_Xs[(size_t)(b*3+0)*NPIX + p];
        float2 X1 = g_Xs[(size_t)(b*3+1)*NPIX + p];
        float2 X2 = g_Xs[(size_t)(b*3+2)*NPIX + p];
        float m0 = sqrtf(X0.x*X0.x + X0.y*X0.y);
        float m1 = sqrtf(X1.x*X1.x + X1.y*X1.y);
        float m2 = sqrtf(X2.x*X2.x + X2.y*X2.y);

        float lg[9];
        #pragma unroll
        for (int o = 0; o < 9; o++) lg[o] = sb2[o];
        for (int j = 0; j < 64; j++) {
            float4 wv = sw1v[j];
            float t = fmaxf(fmaf(wv.z, m2, fmaf(wv.y, m1, fmaf(wv.x, m0, wv.w))), 0.f);
            float4 q0 = sw2v[j*3], q1 = sw2v[j*3+1], q2 = sw2v[j*3+2];
            lg[0] = fmaf(q0.x, t, lg[0]);
            lg[1] = fmaf(q0.y, t, lg[1]);
            lg[2] = fmaf(q0.z, t, lg[2]);
            lg[3] = fmaf(q0.w, t, lg[3]);
            lg[4] = fmaf(q1.x, t, lg[4]);
            lg[5] = fmaf(q1.y, t, lg[5]);
            lg[6] = fmaf(q1.z, t, lg[6]);
            lg[7] = fmaf(q1.w, t, lg[7]);
            lg[8] = fmaf(q2.x, t, lg[8]);
        }

        float mx = lg[0];
        #pragma unroll
        for (int o = 1; o < 9; o++) mx = fmaxf(mx, lg[o]);
        float ssum = 0.f;
        #pragma unroll
        for (int o = 0; o < 9; o++) { lg[o] = __expf(lg[o]-mx); ssum += lg[o]; }
        float inv = __fdividef(1.f, ssum);

        float wp0=0.f, wp1=0.f, wp2=0.f, wq0=0.f, wq1=0.f, wq2=0.f;
        #pragma unroll
        for (int sc = 0; sc < 9; sc++) {
            float a = lg[sc] * inv;
            wp0 = fmaf(a, fp[sc*3+0], wp0);
            wp1 = fmaf(a, fp[sc*3+1], wp1);
            wp2 = fmaf(a, fp[sc*3+2], wp2);
            wq0 = fmaf(a, fm[sc*3+0], wq0);
            wq1 = fmaf(a, fm[sc*3+1], wq1);
            wq2 = fmaf(a, fm[sc*3+2], wq2);
        }
        float2 accp, accm;
        accp.x = X0.x*wp0 + X1.x*wp1 + X2.x*wp2;
        accp.y = X0.y*wp0 + X1.y*wp1 + X2.y*wp2;
        accm.x = X0.x*wq0 + X1.x*wq1 + X2.x*wq2;
        accm.y = -(X0.y*wq0 + X1.y*wq1 + X2.y*wq2);
        g_Att[(size_t)b*NPIX + p]  = accp;
        g_Att[(size_t)b*NPIX + pm] = accm;
    }
}

// ------- inverse: column pass, band mask, fused final stage + store ----------
__global__ void k_inv_col(const float* __restrict__ band)
{
    __shared__ float2 s0[4*N384], s1[4*N384];
    int plane = blockIdx.x / 96;
    int tile  = blockIdx.x - plane*96;
    int kap  = plane / 12;
    int rest = plane - kap*12;
    int del  = rest / 4;
    int beta = rest - del*4;
    float b0 = band[(kap*3+del)*2+0], b1 = band[(kap*3+del)*2+1];
    int si = (int)floorf((b0+1.f)*0.5f*384.f);
    int ei = (int)floorf((b1+1.f)*0.5f*384.f);
    int c0 = tile * 4;
    if (si >= ei || c0 >= ei || c0+4 <= si) return;

    const float2* At = g_Att + (size_t)beta*NPIX;
    for (int idx = threadIdx.x; idx < 4*N384; idx += blockDim.x) {
        int h = idx >> 2, c = idx & 3;
        int wc = c0 + c;
        float2 v = make_float2(0.f, 0.f);
        if (wc >= si && wc < ei && h >= si && h < ei)
            v = At[h*N384 + wc];
        s0[c*N384 + h] = v;
    }
    fft384_pre<4>(s0, s1, threadIdx.x, blockDim.x, +1.f);
    float2* T = g_Tmp + (size_t)plane*NPIX;
    const float sc = 1.f/384.f;
    for (int idx = threadIdx.x; idx < 4*192; idx += blockDim.x) {
        int c = idx / 192, q = idx - c*192;
        int wc = c0 + c;
        if (wc >= si && wc < ei) {
            float2 u = s0[c*N384 + q];
            float2 v = s0[c*N384 + q + 192];
            T[q*N384 + wc]       = make_float2((u.x+v.x)*sc, (u.y+v.y)*sc);
            T[(q+192)*N384 + wc] = make_float2((u.x-v.x)*sc, (u.y-v.y)*sc);
        }
    }
}

// -- inverse row pass: Hermitian-packed, fused final stage + mix/assembly -----
__global__ void k_inv_rowout(const float* __restrict__ band,
                             const float* __restrict__ mixing,
                             float* __restrict__ out)
{
    __shared__ float2 s0[4*N384], s1[4*N384];
    int plane = blockIdx.x / 48;
    int tile  = blockIdx.x - plane*48;
    int n0 = tile * 8;
    int kap  = plane / 12;
    int rest = plane - kap*12;
    int del  = rest / 4;
    int beta = rest - del*4;
    int co = (kap + 2) % 3;
    int ci = (del + 2) % 3;
    int b  = (beta + 2) & 3;
    float b0 = band[(kap*3+del)*2+0], b1 = band[(kap*3+del)*2+1];
    int si = (int)floorf((b0+1.f)*0.5f*384.f);
    int ei = (int)floorf((b1+1.f)*0.5f*384.f);
    float mix = mixing[0];
    float om  = 1.f - mix;
    const float* cv = g_Cv + (size_t)(b*3+ci)*NPIX + (size_t)n0*N384;
    float* ob = out + (size_t)(co*12 + b*3 + ci)*NPIX + (size_t)n0*N384;

    if (si >= ei) {
        for (int idx = threadIdx.x; idx < 8*N384; idx += blockDim.x) {
            float v = om * cv[idx];
            ob[idx]            = v;
            ob[36*NPIX + idx]  = v;
            ob[72*NPIX + idx]  = v;
            ob[108*NPIX + idx] = v;
        }
        return;
    }

    for (int idx = threadIdx.x; idx < 4*N384; idx += blockDim.x)
        s0[idx] = make_float2(0.f, 0.f);
    __syncthreads();
    const float2* Tm = g_Tmp + (size_t)plane*NPIX;
    int K = ei - si;
    for (int j = threadIdx.x; j < 4*K; j += blockDim.x) {
        int c = j & 3;
        int l = si + (j >> 2);
        float2 T1 = Tm[(size_t)(n0 + 2*c)*N384 + l];
        float2 T2 = Tm[(size_t)(n0 + 2*c + 1)*N384 + l];
        float2 zl = make_float2(T1.x - T2.y, T1.y + T2.x);
        float2 zm = make_float2(T1.x + T2.y, T2.x - T1.y);
        int lm = N384 - l;
        if (lm == l) {
            s0[c*N384 + l] = make_float2(zl.x + zm.x, zl.y + zm.y);
        } else {
            s0[c*N384 + l]  = zl;
            s0[c*N384 + lm] = zm;
        }
    }
    fft384_pre<4>(s0, s1, threadIdx.x, blockDim.x, +1.f);
    const float sc = 1.f/768.f;
    for (int idx = threadIdx.x; idx < 4*192; idx += blockDim.x) {
        int c = idx / 192, q = idx - c*192;
        float2 u = s0[c*N384 + q];
        float2 v = s0[c*N384 + q + 192];
        int n1 = n0 + 2*c;
        #pragma unroll
        for (int half = 0; half < 2; half++) {
            int m = q + half*192;
            float re = (half ? (u.x - v.x) : (u.x + v.x)) * sc;
            float im = (half ? (u.y - v.y) : (u.y + v.y)) * sc;
            float v1 = ((n1 + m) & 1) ? -re : re;
            float v2 = ((n1 + 1 + m) & 1) ? -im : im;
            int i1 = (2*c)*N384 + m, i2 = (2*c+1)*N384 + m;
            float o1 = fmaf(mix, v1, om * cv[i1]);
            float o2 = fmaf(mix, v2, om * cv[i2]);
            ob[i1]            = o1;  ob[i2]            = o2;
            ob[36*NPIX + i1]  = o1;  ob[36*NPIX + i2]  = o2;
            ob[72*NPIX + i1]  = o1;  ob[72*NPIX + i2]  = o2;
            ob[108*NPIX + i1] = o1;  ob[108*NPIX + i2] = o2;
        }
    }
}

// ------ spatial 3x3 conv: 4 pixels x 3 out-channels per thread (float4) ------
__global__ void __launch_bounds__(256)
k_conv(const float* __restrict__ x, const float* __restrict__ cw)
{
    __shared__ float scw[81];
    if (threadIdx.x < 81) scw[threadIdx.x] = cw[threadIdx.x];
    __syncthreads();

    int t = blockIdx.x*256 + threadIdx.x;
    int b = t / (NPIX/4);
    int g = t - b*(NPIX/4);
    int p0 = g*4;
    int h = p0 / N384, w0 = p0 - h*N384;

    float acc[3][4];
    #pragma unroll
    for (int o = 0; o < 3; o++)
        #pragma unroll
        for (int j = 0; j < 4; j++) acc[o][j] = 0.f;

    bool hlo = (h > 0), hhi = (h < 383);
    bool wlo = (w0 > 0), whi = (w0 + 4 < N384);

    #pragma unroll
    for (int i = 0; i < 3; i++) {
        const float* base = x + (size_t)(b*3+i)*NPIX;
        float v[3][6];
        #pragma unroll
        for (int kh = 0; kh < 3; kh++) {
            bool ok = (kh == 0) ? hlo : ((kh == 2) ? hhi : true);
            if (ok) {
                const float* row = base + (h + kh - 1)*N384 + w0;
                v[kh][0] = wlo ? row[-1] : 0.f;
                float4 m = *reinterpret_cast<const float4*>(row);
                v[kh][1] = m.x; v[kh][2] = m.y; v[kh][3] = m.z; v[kh][4] = m.w;
                v[kh][5] = whi ? row[4] : 0.f;
            } else {
                #pragma unroll
                for (int k = 0; k < 6; k++) v[kh][k] = 0.f;
            }
        }
        #pragma unroll
        for (int o = 0; o < 3; o++) {
            const float* wq = scw + (o*3+i)*9;
            #pragma unroll
            for (int kh = 0; kh < 3; kh++)
                #pragma unroll
                for (int kw = 0; kw < 3; kw++) {
                    float wv = wq[kh*3+kw];
                    #pragma unroll
                    for (int j = 0; j < 4; j++)
                        acc[o][j] = fmaf(v[kh][j+kw], wv, acc[o][j]);
                }
        }
    }
    #pragma unroll
    for (int o = 0; o < 3; o++) {
        float4 r = make_float4(acc[o][0], acc[o][1], acc[o][2], acc[o][3]);
        *reinterpret_cast<float4*>(&g_Cv[(size_t)(b*3+o)*NPIX + p0]) = r;
    }
}

// ------------------------------------------------------------------
extern "C" void kernel_launch(void* const* d_in, const int* in_sizes, int n_in,
                              void* d_out, int out_size)
{
    const float* x      = (const float*)d_in[0];
    const float* theta  = (const float*)d_in[1];
    const float* sigma  = (const float*)d_in[2];
    const float* f0     = (const float*)d_in[3];
    const float* theta0 = (const float*)d_in[4];
    const float* aw1    = (const float*)d_in[5];
    const float* ab1    = (const float*)d_in[6];
    const float* aw2    = (const float*)d_in[7];
    const float* ab2    = (const float*)d_in[8];
    const float* convw  = (const float*)d_in[9];
    const float* mixing = (const float*)d_in[10];
    const float* band   = (const float*)d_in[11];
    float* out = (float*)d_out;

    k_fwd_row<<<12*48, 256>>>(x);
    k_fwd_col<<<12*49, 256>>>();
    k_attn<<<(HALF_PIX + 255)/256, 256>>>(theta, sigma, f0, theta0, aw1, ab1, aw2, ab2);
    k_conv<<<4*NPIX/4/256, 256>>>(x, convw);
    k_inv_col<<<36*96, 256>>>(band);
    k_inv_rowout<<<36*48, 256>>>(band, mixing, out);
}

// round 15
// speedup vs baseline: 1.1404x; 1.1404x over previous
#include <cuda_runtime.h>
#include <cuda_bf16.h>
#include <math.h>

#define N384 384
#define NPIX (384*384)
#define HALF_PIX (193*384)
#define PI_F 3.14159265358979323846f

// -------- scratch (static __device__ arrays; allocation is forbidden) --------
__device__ float2 g_A  [12*NPIX];
__device__ float2 g_Xs [12*NPIX];
__device__ float2 g_Att[ 4*NPIX];
__device__ float2 g_Tmp[36*NPIX];
__device__ float  g_Cv [12*NPIX];

__device__ __forceinline__ float2 cmul(float2 a, float2 b) {
    return make_float2(a.x*b.x - a.y*b.y, a.x*b.y + a.y*b.x);
}

// ---- 384-pt Stockham FFT, stages 1..4 (radix-3 + 3x radix-4) ----------------
// Input in s0. After return: pre-final data in s0 (synced). Final radix-2
// (twiddle=1): out[q]=u+v, out[q+192]=u-v with u=s0[c*384+q], v=s0[c*384+q+192].
template<int NC>
__device__ void fft384_pre(float2* s0, float2* s1, int tid, int nt, float dir)
{
    __syncthreads();
    {
        const float th0 = dir * (2.0f * PI_F / 384.0f);
        const float s3  = dir * 0.8660254037844386f;
        const int total = NC * 128;
        for (int idx = tid; idx < total; idx += nt) {
            int c = idx >> 7;
            int p = idx & 127;
            const float2* x = s0 + c*N384;
            float2*       y = s1 + c*N384;
            float2 a = x[p], b = x[p+128], cc = x[p+256];
            float t1x = b.x+cc.x, t1y = b.y+cc.y;
            float t2x = b.x-cc.x, t2y = b.y-cc.y;
            float2 x0 = make_float2(a.x+t1x, a.y+t1y);
            float ux = a.x - 0.5f*t1x, uy = a.y - 0.5f*t1y;
            float vx = -s3*t2y,        vy =  s3*t2x;
            float2 x1 = make_float2(ux+vx, uy+vy);
            float2 x2 = make_float2(ux-vx, uy-vy);
            float cw, sw; __sincosf(th0 * (float)p, &sw, &cw);
            float2 w1 = make_float2(cw, sw);
            float2 w2 = cmul(w1, w1);
            y[3*p  ] = x0;
            y[3*p+1] = cmul(x1, w1);
            y[3*p+2] = cmul(x2, w2);
        }
        __syncthreads();
    }
    #pragma unroll
    for (int stage = 0; stage < 3; stage++) {
        const int nn = (stage==0) ? 128 : (stage==1) ? 32 : 8;
        const int ss = (stage==0) ?   3 : (stage==1) ? 12 : 48;
        const int n4 = nn >> 2;
        float2* src = (stage==1) ? s0 : s1;
        float2* dst = (stage==1) ? s1 : s0;
        const float th0 = dir * (2.0f * PI_F / (float)nn);
        const int total = NC * 96;
        for (int idx = tid; idx < total; idx += nt) {
            int c = idx / 96;
            int r = idx - c*96;
            int p = r / ss;
            int q = r - p*ss;
            const float2* x = src + c*N384;
            float2*       y = dst + c*N384;
            float2 x0 = x[q + ss*p];
            float2 x1 = x[q + ss*(p +   n4)];
            float2 x2 = x[q + ss*(p + 2*n4)];
            float2 x3 = x[q + ss*(p + 3*n4)];
            float2 e0 = make_float2(x0.x+x2.x, x0.y+x2.y);
            float2 e1 = make_float2(x1.x+x3.x, x1.y+x3.y);
            float2 d0 = make_float2(x0.x-x2.x, x0.y-x2.y);
            float2 d1 = make_float2(x1.x-x3.x, x1.y-x3.y);
            float2 id1 = make_float2(-dir*d1.y, dir*d1.x);
            float2 u0 = make_float2(e0.x+e1.x,  e0.y+e1.y);
            float2 u1 = make_float2(d0.x+id1.x, d0.y+id1.y);
            float2 u2 = make_float2(e0.x-e1.x,  e0.y-e1.y);
            float2 u3 = make_float2(d0.x-id1.x, d0.y-id1.y);
            float cw, sw; __sincosf(th0 * (float)p, &sw, &cw);
            float2 w1 = make_float2(cw, sw);
            float2 w2 = cmul(w1, w1);
            float2 w3 = cmul(w2, w1);
            y[q + ss*(4*p)  ] = u0;
            y[q + ss*(4*p+1)] = cmul(u1, w1);
            y[q + ss*(4*p+2)] = cmul(u2, w2);
            y[q + ss*(4*p+3)] = cmul(u3, w3);
        }
        __syncthreads();
    }
    // data now in s0, synced
}

// full FFT incl. final radix-2: result in s1
template<int NC>
__device__ void fft384_multi(float2* s0, float2* s1, int tid, int nt, float dir)
{
    fft384_pre<NC>(s0, s1, tid, nt, dir);
    {
        const int total = NC * 192;
        for (int idx = tid; idx < total; idx += nt) {
            int c = idx / 192;
            int q = idx - c*192;
            const float2* x = s0 + c*N384;
            float2*       y = s1 + c*N384;
            float2 a = x[q], b = x[q+192];
            y[q]     = make_float2(a.x+b.x, a.y+b.y);
            y[q+192] = make_float2(a.x-b.x, a.y-b.y);
        }
        __syncthreads();
    }
}

// -------- forward row pass: real-input packing, 8 rows/block -----------------
__global__ void k_fwd_row(const float* __restrict__ x)
{
    __shared__ float2 s0[4*N384], s1[4*N384];
    int img  = blockIdx.x / 48;
    int tile = blockIdx.x - img*48;
    int r0 = tile * 8;
    int b = img / 3, d = img - b*3;
    int bs = (b + 2) & 3;
    int ds = (d + 2) % 3;
    const float* xr = x + ((size_t)(bs*3 + ds)*NPIX) + (size_t)r0*N384;
    for (int idx = threadIdx.x; idx < 4*N384; idx += blockDim.x) {
        int c = idx / N384, w = idx - c*N384;
        s0[idx] = make_float2(xr[(2*c)*N384 + w], xr[(2*c+1)*N384 + w]);
    }
    fft384_multi<4>(s0, s1, threadIdx.x, blockDim.x, -1.f);
    float2* out = g_A + (size_t)img*NPIX + (size_t)r0*N384;
    for (int idx = threadIdx.x; idx < 4*N384; idx += blockDim.x) {
        int c = idx / N384, w = idx - c*N384;
        int mw = (w == 0) ? 0 : (N384 - w);
        float2 F1 = s1[c*N384 + w];
        float2 F2 = s1[c*N384 + mw];
        float2 ev = make_float2(0.5f*(F1.x + F2.x), 0.5f*(F1.y - F2.y));
        float dx = F1.x - F2.x, dy = F1.y + F2.y;
        float2 od = make_float2(0.5f*dy, -0.5f*dx);
        out[(2*c)*N384 + w]   = ev;
        out[(2*c+1)*N384 + w] = od;
    }
}

// -------- forward column pass: Hermitian halving (+h,w shift) ----------------
__global__ void k_fwd_col()
{
    __shared__ float2 s0[4*N384], s1[4*N384];
    int img  = blockIdx.x / 49;
    int tile = blockIdx.x - img*49;
    int c0 = tile * 4;
    const float2* A = g_A + (size_t)img*NPIX;
    for (int idx = threadIdx.x; idx < 4*N384; idx += blockDim.x) {
        int h = idx >> 2, c = idx & 3;
        s0[c*N384 + h] = A[h*N384 + c0 + c];
    }
    fft384_multi<4>(s0, s1, threadIdx.x, blockDim.x, -1.f);
    float2* Xs = g_Xs + (size_t)img*NPIX;
    for (int idx = threadIdx.x; idx < 4*N384; idx += blockDim.x) {
        int hh = idx >> 2, c = idx & 3;
        int l = c0 + c;
        float2 v = s1[c*N384 + hh];
        if (l <= 192) {
            int h2 = hh + 192; if (h2 >= N384) h2 -= N384;
            int w2 = l + 192;  if (w2 >= N384) w2 -= N384;
            Xs[h2*N384 + w2] = v;
        }
        if (l >= 1 && l <= 191) {
            int hm = ((N384 - hh) % N384) + 192; if (hm >= N384) hm -= N384;
            int wm = 192 - l;
            Xs[hm*N384 + wm] = make_float2(v.x, -v.y);
        }
    }
}

// --- fused attention: half-plane MLP + softmax + filt(p & mirror) + combine --
__global__ void __launch_bounds__(256)
k_attn(const float* __restrict__ theta, const float* __restrict__ sigma,
       const float* __restrict__ f0,    const float* __restrict__ theta0,
       const float* __restrict__ w1,    const float* __restrict__ b1,
       const float* __restrict__ w2,    const float* __restrict__ b2)
{
    __shared__ float4 sw1v[64];
    __shared__ float4 sw2v[192];
    __shared__ float  sb2[9];
    __shared__ float  sth[27], slf0[27], sc1[27], sc2[27];
    __shared__ int    s_uni;
    int tid = threadIdx.x;
    if (tid < 64)
        sw1v[tid] = make_float4(w1[tid*3], w1[tid*3+1], w1[tid*3+2], b1[tid]);
    for (int i = tid; i < 192; i += 256) {
        int j = i / 3, k = i - 3*j;
        int o0 = k*4;
        sw2v[i] = make_float4(w2[o0*64 + j],
                              (o0+1 < 9) ? w2[(o0+1)*64 + j] : 0.f,
                              (o0+2 < 9) ? w2[(o0+2)*64 + j] : 0.f,
                              (o0+3 < 9) ? w2[(o0+3)*64 + j] : 0.f);
    }
    if (tid < 9) sb2[tid] = b2[tid];
    if (tid < 27) {
        sth[tid]  = theta[tid];
        float ls  = __logf(sigma[tid]);
        sc1[tid]  = -0.5f / (ls*ls);
        float t0  = theta0[tid];
        sc2[tid]  = -0.5f / (t0*t0);
        slf0[tid] = __logf(f0[tid]);
    }
    __syncthreads();
    if (tid == 0) {
        int u = 1;
        #pragma unroll
        for (int i = 1; i < 27; i++) if (slf0[i] != slf0[0]) u = 0;
        s_uni = u;
    }
    __syncthreads();
    const int uni = s_uni;

    int p = blockIdx.x*256 + tid;
    if (p >= HALF_PIX) return;
    int h = p / N384, w = p - h*N384;
    int hm = (N384 - h) % N384;
    int wm = (N384 - w) % N384;
    int pm = hm*N384 + wm;

    float fp[27], fm[27];
    {
        float yy = -1.f + (2.f/383.f) * (float)h;
        float xx = -1.f + (2.f/383.f) * (float)w;
        float r   = sqrtf(xx*xx + yy*yy + 1e-6f);
        float phi = atan2f(yy, xx);
        float ym = -1.f + (2.f/383.f) * (float)hm;
        float xm = -1.f + (2.f/383.f) * (float)wm;
        float rm   = sqrtf(xm*xm + ym*ym + 1e-6f);
        float phim = atan2f(ym, xm);
        if (uni) {
            float lr = __logf(r - slf0[0]);   float lr2 = lr*lr;
            float lm = __logf(rm - slf0[0]);  float lm2 = lm*lm;
            #pragma unroll
            for (int i = 0; i < 27; i++) {
                float dp = phi  - sth[i];
                float dm = phim - sth[i];
                fp[i] = __expf(fmaf(lr2, sc1[i], dp*dp*sc2[i]));
                fm[i] = __expf(fmaf(lm2, sc1[i], dm*dm*sc2[i]));
            }
        } else {
            #pragma unroll
            for (int i = 0; i < 27; i++) {
                float lr = __logf(r  - slf0[i]);
                float lm = __logf(rm - slf0[i]);
                float dp = phi  - sth[i];
                float dm = phim - sth[i];
                fp[i] = __expf(fmaf(lr*lr, sc1[i], dp*dp*sc2[i]));
                fm[i] = __expf(fmaf(lm*lm, sc1[i], dm*dm*sc2[i]));
            }
        }
    }

    #pragma unroll
    for (int b = 0; b < 4; b++) {
        float2 X0 = g_Xs[(size_t)(b*3+0)*NPIX + p];
        float2 X1 = g_Xs[(size_t)(b*3+1)*NPIX + p];
        float2 X2 = g_Xs[(size_t)(b*3+2)*NPIX + p];
        float m0 = sqrtf(X0.x*X0.x + X0.y*X0.y);
        float m1 = sqrtf(X1.x*X1.x + X1.y*X1.y);
        float m2 = sqrtf(X2.x*X2.x + X2.y*X2.y);

        float lg[9];
        #pragma unroll
        for (int o = 0; o < 9; o++) lg[o] = sb2[o];
        for (int j = 0; j < 64; j++) {
            float4 wv = sw1v[j];
            float t = fmaxf(fmaf(wv.z, m2, fmaf(wv.y, m1, fmaf(wv.x, m0, wv.w))), 0.f);
            float4 q0 = sw2v[j*3], q1 = sw2v[j*3+1], q2 = sw2v[j*3+2];
            lg[0] = fmaf(q0.x, t, lg[0]);
            lg[1] = fmaf(q0.y, t, lg[1]);
            lg[2] = fmaf(q0.z, t, lg[2]);
            lg[3] = fmaf(q0.w, t, lg[3]);
            lg[4] = fmaf(q1.x, t, lg[4]);
            lg[5] = fmaf(q1.y, t, lg[5]);
            lg[6] = fmaf(q1.z, t, lg[6]);
            lg[7] = fmaf(q1.w, t, lg[7]);
            lg[8] = fmaf(q2.x, t, lg[8]);
        }

        float mx = lg[0];
        #pragma unroll
        for (int o = 1; o < 9; o++) mx = fmaxf(mx, lg[o]);
        float ssum = 0.f;
        #pragma unroll
        for (int o = 0; o < 9; o++) { lg[o] = __expf(lg[o]-mx); ssum += lg[o]; }
        float inv = __fdividef(1.f, ssum);

        float wp0=0.f, wp1=0.f, wp2=0.f, wq0=0.f, wq1=0.f, wq2=0.f;
        #pragma unroll
        for (int sc = 0; sc < 9; sc++) {
            float a = lg[sc] * inv;
            wp0 = fmaf(a, fp[sc*3+0], wp0);
            wp1 = fmaf(a, fp[sc*3+1], wp1);
            wp2 = fmaf(a, fp[sc*3+2], wp2);
            wq0 = fmaf(a, fm[sc*3+0], wq0);
            wq1 = fmaf(a, fm[sc*3+1], wq1);
            wq2 = fmaf(a, fm[sc*3+2], wq2);
        }
        float2 accp, accm;
        accp.x = X0.x*wp0 + X1.x*wp1 + X2.x*wp2;
        accp.y = X0.y*wp0 + X1.y*wp1 + X2.y*wp2;
        accm.x = X0.x*wq0 + X1.x*wq1 + X2.x*wq2;
        accm.y = -(X0.y*wq0 + X1.y*wq1 + X2.y*wq2);
        g_Att[(size_t)b*NPIX + p]  = accp;
        g_Att[(size_t)b*NPIX + pm] = accm;
    }
}

// ---------------- inverse: column pass with band mask (pruned) ---------------
__global__ void k_inv_col(const float* __restrict__ band)
{
    __shared__ float2 s0[4*N384], s1[4*N384];
    int plane = blockIdx.x / 96;
    int tile  = blockIdx.x - plane*96;
    int kap  = plane / 12;
    int rest = plane - kap*12;
    int del  = rest / 4;
    int beta = rest - del*4;
    float b0 = band[(kap*3+del)*2+0], b1 = band[(kap*3+del)*2+1];
    int si = (int)floorf((b0+1.f)*0.5f*384.f);
    int ei = (int)floorf((b1+1.f)*0.5f*384.f);
    int c0 = tile * 4;
    if (si >= ei || c0 >= ei || c0+4 <= si) return;

    const float2* At = g_Att + (size_t)beta*NPIX;
    for (int idx = threadIdx.x; idx < 4*N384; idx += blockDim.x) {
        int h = idx >> 2, c = idx & 3;
        int wc = c0 + c;
        float2 v = make_float2(0.f, 0.f);
        if (wc >= si && wc < ei && h >= si && h < ei)
            v = At[h*N384 + wc];
        s0[c*N384 + h] = v;
    }
    fft384_multi<4>(s0, s1, threadIdx.x, blockDim.x, +1.f);
    float2* T = g_Tmp + (size_t)plane*NPIX;
    const float sc = 1.f/384.f;
    for (int idx = threadIdx.x; idx < 4*N384; idx += blockDim.x) {
        int n = idx >> 2, c = idx & 3;
        int wc = c0 + c;
        if (wc >= si && wc < ei) {
            float2 v = s1[c*N384 + n];
            T[n*N384 + wc] = make_float2(v.x*sc, v.y*sc);
        }
    }
}

// -- inverse row pass: Hermitian-packed, fused final stage + mix/assembly -----
// (fused stores are coalesced here: consecutive q -> consecutive i1/i2)
__global__ void k_inv_rowout(const float* __restrict__ band,
                             const float* __restrict__ mixing,
                             float* __restrict__ out)
{
    __shared__ float2 s0[4*N384], s1[4*N384];
    int plane = blockIdx.x / 48;
    int tile  = blockIdx.x - plane*48;
    int n0 = tile * 8;
    int kap  = plane / 12;
    int rest = plane - kap*12;
    int del  = rest / 4;
    int beta = rest - del*4;
    int co = (kap + 2) % 3;
    int ci = (del + 2) % 3;
    int b  = (beta + 2) & 3;
    float b0 = band[(kap*3+del)*2+0], b1 = band[(kap*3+del)*2+1];
    int si = (int)floorf((b0+1.f)*0.5f*384.f);
    int ei = (int)floorf((b1+1.f)*0.5f*384.f);
    float mix = mixing[0];
    float om  = 1.f - mix;
    const float* cv = g_Cv + (size_t)(b*3+ci)*NPIX + (size_t)n0*N384;
    float* ob = out + (size_t)(co*12 + b*3 + ci)*NPIX + (size_t)n0*N384;

    if (si >= ei) {
        for (int idx = threadIdx.x; idx < 8*N384; idx += blockDim.x) {
            float v = om * cv[idx];
            ob[idx]            = v;
            ob[36*NPIX + idx]  = v;
            ob[72*NPIX + idx]  = v;
            ob[108*NPIX + idx] = v;
        }
        return;
    }

    for (int idx = threadIdx.x; idx < 4*N384; idx += blockDim.x)
        s0[idx] = make_float2(0.f, 0.f);
    __syncthreads();
    const float2* Tm = g_Tmp + (size_t)plane*NPIX;
    int K = ei - si;
    for (int j = threadIdx.x; j < 4*K; j += blockDim.x) {
        int c = j & 3;
        int l = si + (j >> 2);
        float2 T1 = Tm[(size_t)(n0 + 2*c)*N384 + l];
        float2 T2 = Tm[(size_t)(n0 + 2*c + 1)*N384 + l];
        float2 zl = make_float2(T1.x - T2.y, T1.y + T2.x);
        float2 zm = make_float2(T1.x + T2.y, T2.x - T1.y);
        int lm = N384 - l;
        if (lm == l) {
            s0[c*N384 + l] = make_float2(zl.x + zm.x, zl.y + zm.y);
        } else {
            s0[c*N384 + l]  = zl;
            s0[c*N384 + lm] = zm;
        }
    }
    fft384_pre<4>(s0, s1, threadIdx.x, blockDim.x, +1.f);
    const float sc = 1.f/768.f;
    for (int idx = threadIdx.x; idx < 4*192; idx += blockDim.x) {
        int c = idx / 192, q = idx - c*192;
        float2 u = s0[c*N384 + q];
        float2 v = s0[c*N384 + q + 192];
        int n1 = n0 + 2*c;
        #pragma unroll
        for (int half = 0; half < 2; half++) {
            int m = q + half*192;
            float re = (half ? (u.x - v.x) : (u.x + v.x)) * sc;
            float im = (half ? (u.y - v.y) : (u.y + v.y)) * sc;
            float v1 = ((n1 + m) & 1) ? -re : re;
            float v2 = ((n1 + 1 + m) & 1) ? -im : im;
            int i1 = (2*c)*N384 + m, i2 = (2*c+1)*N384 + m;
            float o1 = fmaf(mix, v1, om * cv[i1]);
            float o2 = fmaf(mix, v2, om * cv[i2]);
            ob[i1]            = o1;  ob[i2]            = o2;
            ob[36*NPIX + i1]  = o1;  ob[36*NPIX + i2]  = o2;
            ob[72*NPIX + i1]  = o1;  ob[72*NPIX + i2]  = o2;
            ob[108*NPIX + i1] = o1;  ob[108*NPIX + i2] = o2;
        }
    }
}

// ------ spatial 3x3 conv: 4 pixels x 3 out-channels per thread (float4) ------
__global__ void __launch_bounds__(256)
k_conv(const float* __restrict__ x, const float* __restrict__ cw)
{
    __shared__ float scw[81];
    if (threadIdx.x < 81) scw[threadIdx.x] = cw[threadIdx.x];
    __syncthreads();

    int t = blockIdx.x*256 + threadIdx.x;
    int b = t / (NPIX/4);
    int g = t - b*(NPIX/4);
    int p0 = g*4;
    int h = p0 / N384, w0 = p0 - h*N384;

    float acc[3][4];
    #pragma unroll
    for (int o = 0; o < 3; o++)
        #pragma unroll
        for (int j = 0; j < 4; j++) acc[o][j] = 0.f;

    bool hlo = (h > 0), hhi = (h < 383);
    bool wlo = (w0 > 0), whi = (w0 + 4 < N384);

    #pragma unroll
    for (int i = 0; i < 3; i++) {
        const float* base = x + (size_t)(b*3+i)*NPIX;
        float v[3][6];
        #pragma unroll
        for (int kh = 0; kh < 3; kh++) {
            bool ok = (kh == 0) ? hlo : ((kh == 2) ? hhi : true);
            if (ok) {
                const float* row = base + (h + kh - 1)*N384 + w0;
                v[kh][0] = wlo ? row[-1] : 0.f;
                float4 m = *reinterpret_cast<const float4*>(row);
                v[kh][1] = m.x; v[kh][2] = m.y; v[kh][3] = m.z; v[kh][4] = m.w;
                v[kh][5] = whi ? row[4] : 0.f;
            } else {
                #pragma unroll
                for (int k = 0; k < 6; k++) v[kh][k] = 0.f;
            }
        }
        #pragma unroll
        for (int o = 0; o < 3; o++) {
            const float* wq = scw + (o*3+i)*9;
            #pragma unroll
            for (int kh = 0; kh < 3; kh++)
                #pragma unroll
                for (int kw = 0; kw < 3; kw++) {
                    float wv = wq[kh*3+kw];
                    #pragma unroll
                    for (int j = 0; j < 4; j++)
                        acc[o][j] = fmaf(v[kh][j+kw], wv, acc[o][j]);
                }
        }
    }
    #pragma unroll
    for (int o = 0; o < 3; o++) {
        float4 r = make_float4(acc[o][0], acc[o][1], acc[o][2], acc[o][3]);
        *reinterpret_cast<float4*>(&g_Cv[(size_t)(b*3+o)*NPIX + p0]) = r;
    }
}

// ------------------------------------------------------------------
extern "C" void kernel_launch(void* const* d_in, const int* in_sizes, int n_in,
                              void* d_out, int out_size)
{
    const float* x      = (const float*)d_in[0];
    const float* theta  = (const float*)d_in[1];
    const float* sigma  = (const float*)d_in[2];
    const float* f0     = (const float*)d_in[3];
    const float* theta0 = (const float*)d_in[4];
    const float* aw1    = (const float*)d_in[5];
    const float* ab1    = (const float*)d_in[6];
    const float* aw2    = (const float*)d_in[7];
    const float* ab2    = (const float*)d_in[8];
    const float* convw  = (const float*)d_in[9];
    const float* mixing = (const float*)d_in[10];
    const float* band   = (const float*)d_in[11];
    float* out = (float*)d_out;

    k_fwd_row<<<12*48, 256>>>(x);
    k_fwd_col<<<12*49, 256>>>();
    k_attn<<<(HALF_PIX + 255)/256, 256>>>(theta, sigma, f0, theta0, aw1, ab1, aw2, ab2);
    k_conv<<<4*NPIX/4/256, 256>>>(x, convw);
    k_inv_col<<<36*96, 256>>>(band);
    k_inv_rowout<<<36*48, 256>>>(band, mixing, out);
}

// round 16
// speedup vs baseline: 1.1721x; 1.0277x over previous
#include <cuda_runtime.h>
#include <cuda_bf16.h>
#include <math.h>

#define N384 384
#define NPIX (384*384)
#define HALF_PIX (193*384)
#define PI_F 3.14159265358979323846f

// -------- scratch (static __device__ arrays; allocation is forbidden) --------
__device__ float2 g_A  [12*NPIX];
__device__ float2 g_Xs [12*NPIX];
__device__ float2 g_Att[ 4*NPIX];
__device__ float2 g_Tmp[36*NPIX];
__device__ float  g_Cv [12*NPIX];

__device__ __forceinline__ float2 cmul(float2 a, float2 b) {
    return make_float2(a.x*b.x - a.y*b.y, a.x*b.y + a.y*b.x);
}

// ---- 384-pt Stockham FFT, stages 1..4 (radix-3 + 3x radix-4) ----------------
template<int NC>
__device__ void fft384_pre(float2* s0, float2* s1, int tid, int nt, float dir)
{
    __syncthreads();
    {
        const float th0 = dir * (2.0f * PI_F / 384.0f);
        const float s3  = dir * 0.8660254037844386f;
        const int total = NC * 128;
        for (int idx = tid; idx < total; idx += nt) {
            int c = idx >> 7;
            int p = idx & 127;
            const float2* x = s0 + c*N384;
            float2*       y = s1 + c*N384;
            float2 a = x[p], b = x[p+128], cc = x[p+256];
            float t1x = b.x+cc.x, t1y = b.y+cc.y;
            float t2x = b.x-cc.x, t2y = b.y-cc.y;
            float2 x0 = make_float2(a.x+t1x, a.y+t1y);
            float ux = a.x - 0.5f*t1x, uy = a.y - 0.5f*t1y;
            float vx = -s3*t2y,        vy =  s3*t2x;
            float2 x1 = make_float2(ux+vx, uy+vy);
            float2 x2 = make_float2(ux-vx, uy-vy);
            float cw, sw; __sincosf(th0 * (float)p, &sw, &cw);
            float2 w1 = make_float2(cw, sw);
            float2 w2 = cmul(w1, w1);
            y[3*p  ] = x0;
            y[3*p+1] = cmul(x1, w1);
            y[3*p+2] = cmul(x2, w2);
        }
        __syncthreads();
    }
    #pragma unroll
    for (int stage = 0; stage < 3; stage++) {
        const int nn = (stage==0) ? 128 : (stage==1) ? 32 : 8;
        const int ss = (stage==0) ?   3 : (stage==1) ? 12 : 48;
        const int n4 = nn >> 2;
        float2* src = (stage==1) ? s0 : s1;
        float2* dst = (stage==1) ? s1 : s0;
        const float th0 = dir * (2.0f * PI_F / (float)nn);
        const int total = NC * 96;
        for (int idx = tid; idx < total; idx += nt) {
            int c = idx / 96;
            int r = idx - c*96;
            int p = r / ss;
            int q = r - p*ss;
            const float2* x = src + c*N384;
            float2*       y = dst + c*N384;
            float2 x0 = x[q + ss*p];
            float2 x1 = x[q + ss*(p +   n4)];
            float2 x2 = x[q + ss*(p + 2*n4)];
            float2 x3 = x[q + ss*(p + 3*n4)];
            float2 e0 = make_float2(x0.x+x2.x, x0.y+x2.y);
            float2 e1 = make_float2(x1.x+x3.x, x1.y+x3.y);
            float2 d0 = make_float2(x0.x-x2.x, x0.y-x2.y);
            float2 d1 = make_float2(x1.x-x3.x, x1.y-x3.y);
            float2 id1 = make_float2(-dir*d1.y, dir*d1.x);
            float2 u0 = make_float2(e0.x+e1.x,  e0.y+e1.y);
            float2 u1 = make_float2(d0.x+id1.x, d0.y+id1.y);
            float2 u2 = make_float2(e0.x-e1.x,  e0.y-e1.y);
            float2 u3 = make_float2(d0.x-id1.x, d0.y-id1.y);
            float cw, sw; __sincosf(th0 * (float)p, &sw, &cw);
            float2 w1 = make_float2(cw, sw);
            float2 w2 = cmul(w1, w1);
            float2 w3 = cmul(w2, w1);
            y[q + ss*(4*p)  ] = u0;
            y[q + ss*(4*p+1)] = cmul(u1, w1);
            y[q + ss*(4*p+2)] = cmul(u2, w2);
            y[q + ss*(4*p+3)] = cmul(u3, w3);
        }
        __syncthreads();
    }
}

// full FFT incl. final radix-2: result in s1
template<int NC>
__device__ void fft384_multi(float2* s0, float2* s1, int tid, int nt, float dir)
{
    fft384_pre<NC>(s0, s1, tid, nt, dir);
    {
        const int total = NC * 192;
        for (int idx = tid; idx < total; idx += nt) {
            int c = idx / 192;
            int q = idx - c*192;
            const float2* x = s0 + c*N384;
            float2*       y = s1 + c*N384;
            float2 a = x[q], b = x[q+192];
            y[q]     = make_float2(a.x+b.x, a.y+b.y);
            y[q+192] = make_float2(a.x-b.x, a.y-b.y);
        }
        __syncthreads();
    }
}

// -------- forward row pass: real-input packing, 8 rows/block -----------------
__global__ void k_fwd_row(const float* __restrict__ x)
{
    __shared__ float2 s0[4*N384], s1[4*N384];
    int img  = blockIdx.x / 48;
    int tile = blockIdx.x - img*48;
    int r0 = tile * 8;
    int b = img / 3, d = img - b*3;
    int bs = (b + 2) & 3;
    int ds = (d + 2) % 3;
    const float* xr = x + ((size_t)(bs*3 + ds)*NPIX) + (size_t)r0*N384;
    for (int idx = threadIdx.x; idx < 4*N384; idx += blockDim.x) {
        int c = idx / N384, w = idx - c*N384;
        s0[idx] = make_float2(xr[(2*c)*N384 + w], xr[(2*c+1)*N384 + w]);
    }
    fft384_multi<4>(s0, s1, threadIdx.x, blockDim.x, -1.f);
    float2* out = g_A + (size_t)img*NPIX + (size_t)r0*N384;
    for (int idx = threadIdx.x; idx < 4*N384; idx += blockDim.x) {
        int c = idx / N384, w = idx - c*N384;
        int mw = (w == 0) ? 0 : (N384 - w);
        float2 F1 = s1[c*N384 + w];
        float2 F2 = s1[c*N384 + mw];
        float2 ev = make_float2(0.5f*(F1.x + F2.x), 0.5f*(F1.y - F2.y));
        float dx = F1.x - F2.x, dy = F1.y + F2.y;
        float2 od = make_float2(0.5f*dy, -0.5f*dx);
        out[(2*c)*N384 + w]   = ev;
        out[(2*c+1)*N384 + w] = od;
    }
}

// -------- forward column pass: Hermitian halving (+h,w shift) ----------------
__global__ void k_fwd_col()
{
    __shared__ float2 s0[4*N384], s1[4*N384];
    int img  = blockIdx.x / 49;
    int tile = blockIdx.x - img*49;
    int c0 = tile * 4;
    const float2* A = g_A + (size_t)img*NPIX;
    for (int idx = threadIdx.x; idx < 4*N384; idx += blockDim.x) {
        int h = idx >> 2, c = idx & 3;
        s0[c*N384 + h] = A[h*N384 + c0 + c];
    }
    fft384_multi<4>(s0, s1, threadIdx.x, blockDim.x, -1.f);
    float2* Xs = g_Xs + (size_t)img*NPIX;
    for (int idx = threadIdx.x; idx < 4*N384; idx += blockDim.x) {
        int hh = idx >> 2, c = idx & 3;
        int l = c0 + c;
        float2 v = s1[c*N384 + hh];
        if (l <= 192) {
            int h2 = hh + 192; if (h2 >= N384) h2 -= N384;
            int w2 = l + 192;  if (w2 >= N384) w2 -= N384;
            Xs[h2*N384 + w2] = v;
        }
        if (l >= 1 && l <= 191) {
            int hm = ((N384 - hh) % N384) + 192; if (hm >= N384) hm -= N384;
            int wm = 192 - l;
            Xs[hm*N384 + wm] = make_float2(v.x, -v.y);
        }
    }
}

// --- fused attention: half-plane, 2 batches per MLP pass (shared weight LDS) --
__global__ void __launch_bounds__(256)
k_attn(const float* __restrict__ theta, const float* __restrict__ sigma,
       const float* __restrict__ f0,    const float* __restrict__ theta0,
       const float* __restrict__ w1,    const float* __restrict__ b1,
       const float* __restrict__ w2,    const float* __restrict__ b2)
{
    __shared__ float4 sw1v[64];
    __shared__ float4 sw2v[192];
    __shared__ float  sb2[9];
    __shared__ float  sth[27], slf0[27], sc1[27], sc2[27];
    __shared__ int    s_uni;
    int tid = threadIdx.x;
    if (tid < 64)
        sw1v[tid] = make_float4(w1[tid*3], w1[tid*3+1], w1[tid*3+2], b1[tid]);
    for (int i = tid; i < 192; i += 256) {
        int j = i / 3, k = i - 3*j;
        int o0 = k*4;
        sw2v[i] = make_float4(w2[o0*64 + j],
                              (o0+1 < 9) ? w2[(o0+1)*64 + j] : 0.f,
                              (o0+2 < 9) ? w2[(o0+2)*64 + j] : 0.f,
                              (o0+3 < 9) ? w2[(o0+3)*64 + j] : 0.f);
    }
    if (tid < 9) sb2[tid] = b2[tid];
    if (tid < 27) {
        sth[tid]  = theta[tid];
        float ls  = __logf(sigma[tid]);
        sc1[tid]  = -0.5f / (ls*ls);
        float t0  = theta0[tid];
        sc2[tid]  = -0.5f / (t0*t0);
        slf0[tid] = __logf(f0[tid]);
    }
    __syncthreads();
    if (tid == 0) {
        int u = 1;
        #pragma unroll
        for (int i = 1; i < 27; i++) if (slf0[i] != slf0[0]) u = 0;
        s_uni = u;
    }
    __syncthreads();
    const int uni = s_uni;

    int p = blockIdx.x*256 + tid;
    if (p >= HALF_PIX) return;
    int h = p / N384, w = p - h*N384;
    int hm = (N384 - h) % N384;
    int wm = (N384 - w) % N384;
    int pm = hm*N384 + wm;

    float fp[27], fm[27];
    {
        float yy = -1.f + (2.f/383.f) * (float)h;
        float xx = -1.f + (2.f/383.f) * (float)w;
        float r   = sqrtf(xx*xx + yy*yy + 1e-6f);
        float phi = atan2f(yy, xx);
        float ym = -1.f + (2.f/383.f) * (float)hm;
        float xm = -1.f + (2.f/383.f) * (float)wm;
        float rm   = sqrtf(xm*xm + ym*ym + 1e-6f);
        float phim = atan2f(ym, xm);
        if (uni) {
            float lr = __logf(r - slf0[0]);   float lr2 = lr*lr;
            float lmm = __logf(rm - slf0[0]); float lm2 = lmm*lmm;
            #pragma unroll
            for (int i = 0; i < 27; i++) {
                float dp = phi  - sth[i];
                float dm = phim - sth[i];
                fp[i] = __expf(fmaf(lr2, sc1[i], dp*dp*sc2[i]));
                fm[i] = __expf(fmaf(lm2, sc1[i], dm*dm*sc2[i]));
            }
        } else {
            #pragma unroll
            for (int i = 0; i < 27; i++) {
                float lr  = __logf(r  - slf0[i]);
                float lmm = __logf(rm - slf0[i]);
                float dp = phi  - sth[i];
                float dm = phim - sth[i];
                fp[i] = __expf(fmaf(lr*lr,   sc1[i], dp*dp*sc2[i]));
                fm[i] = __expf(fmaf(lmm*lmm, sc1[i], dm*dm*sc2[i]));
            }
        }
    }

    // ---- 2 passes x 2 batches: MLP shares weight loads across the pair ----
    #pragma unroll
    for (int pass = 0; pass < 2; pass++) {
        int bA = pass*2, bB = pass*2 + 1;
        float2 XA0 = g_Xs[(size_t)(bA*3+0)*NPIX + p];
        float2 XA1 = g_Xs[(size_t)(bA*3+1)*NPIX + p];
        float2 XA2 = g_Xs[(size_t)(bA*3+2)*NPIX + p];
        float2 XB0 = g_Xs[(size_t)(bB*3+0)*NPIX + p];
        float2 XB1 = g_Xs[(size_t)(bB*3+1)*NPIX + p];
        float2 XB2 = g_Xs[(size_t)(bB*3+2)*NPIX + p];
        float mA0 = sqrtf(XA0.x*XA0.x + XA0.y*XA0.y);
        float mA1 = sqrtf(XA1.x*XA1.x + XA1.y*XA1.y);
        float mA2 = sqrtf(XA2.x*XA2.x + XA2.y*XA2.y);
        float mB0 = sqrtf(XB0.x*XB0.x + XB0.y*XB0.y);
        float mB1 = sqrtf(XB1.x*XB1.x + XB1.y*XB1.y);
        float mB2 = sqrtf(XB2.x*XB2.x + XB2.y*XB2.y);

        float lg[18];
        #pragma unroll
        for (int o = 0; o < 9; o++) { lg[o] = sb2[o]; lg[9+o] = sb2[o]; }
        for (int j = 0; j < 64; j++) {
            float4 wv = sw1v[j];
            float tA = fmaxf(fmaf(wv.z, mA2, fmaf(wv.y, mA1, fmaf(wv.x, mA0, wv.w))), 0.f);
            float tB = fmaxf(fmaf(wv.z, mB2, fmaf(wv.y, mB1, fmaf(wv.x, mB0, wv.w))), 0.f);
            float4 q0 = sw2v[j*3], q1 = sw2v[j*3+1], q2 = sw2v[j*3+2];
            lg[0] = fmaf(q0.x, tA, lg[0]);  lg[9]  = fmaf(q0.x, tB, lg[9]);
            lg[1] = fmaf(q0.y, tA, lg[1]);  lg[10] = fmaf(q0.y, tB, lg[10]);
            lg[2] = fmaf(q0.z, tA, lg[2]);  lg[11] = fmaf(q0.z, tB, lg[11]);
            lg[3] = fmaf(q0.w, tA, lg[3]);  lg[12] = fmaf(q0.w, tB, lg[12]);
            lg[4] = fmaf(q1.x, tA, lg[4]);  lg[13] = fmaf(q1.x, tB, lg[13]);
            lg[5] = fmaf(q1.y, tA, lg[5]);  lg[14] = fmaf(q1.y, tB, lg[14]);
            lg[6] = fmaf(q1.z, tA, lg[6]);  lg[15] = fmaf(q1.z, tB, lg[15]);
            lg[7] = fmaf(q1.w, tA, lg[7]);  lg[16] = fmaf(q1.w, tB, lg[16]);
            lg[8] = fmaf(q2.x, tA, lg[8]);  lg[17] = fmaf(q2.x, tB, lg[17]);
        }

        #pragma unroll
        for (int half = 0; half < 2; half++) {
            float* l9 = lg + half*9;
            float mx = l9[0];
            #pragma unroll
            for (int o = 1; o < 9; o++) mx = fmaxf(mx, l9[o]);
            float ssum = 0.f;
            #pragma unroll
            for (int o = 0; o < 9; o++) { l9[o] = __expf(l9[o]-mx); ssum += l9[o]; }
            float inv = __fdividef(1.f, ssum);

            float wp0=0.f, wp1=0.f, wp2=0.f, wq0=0.f, wq1=0.f, wq2=0.f;
            #pragma unroll
            for (int sc = 0; sc < 9; sc++) {
                float a = l9[sc] * inv;
                wp0 = fmaf(a, fp[sc*3+0], wp0);
                wp1 = fmaf(a, fp[sc*3+1], wp1);
                wp2 = fmaf(a, fp[sc*3+2], wp2);
                wq0 = fmaf(a, fm[sc*3+0], wq0);
                wq1 = fmaf(a, fm[sc*3+1], wq1);
                wq2 = fmaf(a, fm[sc*3+2], wq2);
            }
            float2 X0 = half ? XB0 : XA0;
            float2 X1 = half ? XB1 : XA1;
            float2 X2 = half ? XB2 : XA2;
            int bb = half ? bB : bA;
            float2 accp, accm;
            accp.x = X0.x*wp0 + X1.x*wp1 + X2.x*wp2;
            accp.y = X0.y*wp0 + X1.y*wp1 + X2.y*wp2;
            accm.x = X0.x*wq0 + X1.x*wq1 + X2.x*wq2;     // Xs[pm] = conj(Xs[p])
            accm.y = -(X0.y*wq0 + X1.y*wq1 + X2.y*wq2);
            g_Att[(size_t)bb*NPIX + p]  = accp;
            g_Att[(size_t)bb*NPIX + pm] = accm;
        }
    }
}

// ---------------- inverse: column pass with band mask (pruned) ---------------
__global__ void k_inv_col(const float* __restrict__ band)
{
    __shared__ float2 s0[4*N384], s1[4*N384];
    int plane = blockIdx.x / 96;
    int tile  = blockIdx.x - plane*96;
    int kap  = plane / 12;
    int rest = plane - kap*12;
    int del  = rest / 4;
    int beta = rest - del*4;
    float b0 = band[(kap*3+del)*2+0], b1 = band[(kap*3+del)*2+1];
    int si = (int)floorf((b0+1.f)*0.5f*384.f);
    int ei = (int)floorf((b1+1.f)*0.5f*384.f);
    int c0 = tile * 4;
    if (si >= ei || c0 >= ei || c0+4 <= si) return;

    const float2* At = g_Att + (size_t)beta*NPIX;
    for (int idx = threadIdx.x; idx < 4*N384; idx += blockDim.x) {
        int h = idx >> 2, c = idx & 3;
        int wc = c0 + c;
        float2 v = make_float2(0.f, 0.f);
        if (wc >= si && wc < ei && h >= si && h < ei)
            v = At[h*N384 + wc];
        s0[c*N384 + h] = v;
    }
    fft384_multi<4>(s0, s1, threadIdx.x, blockDim.x, +1.f);
    float2* T = g_Tmp + (size_t)plane*NPIX;
    const float sc = 1.f/384.f;
    for (int idx = threadIdx.x; idx < 4*N384; idx += blockDim.x) {
        int n = idx >> 2, c = idx & 3;
        int wc = c0 + c;
        if (wc >= si && wc < ei) {
            float2 v = s1[c*N384 + n];
            T[n*N384 + wc] = make_float2(v.x*sc, v.y*sc);
        }
    }
}

// -- inverse row pass: Hermitian-packed, fused final stage + mix/assembly -----
__global__ void k_inv_rowout(const float* __restrict__ band,
                             const float* __restrict__ mixing,
                             float* __restrict__ out)
{
    __shared__ float2 s0[4*N384], s1[4*N384];
    int plane = blockIdx.x / 48;
    int tile  = blockIdx.x - plane*48;
    int n0 = tile * 8;
    int kap  = plane / 12;
    int rest = plane - kap*12;
    int del  = rest / 4;
    int beta = rest - del*4;
    int co = (kap + 2) % 3;
    int ci = (del + 2) % 3;
    int b  = (beta + 2) & 3;
    float b0 = band[(kap*3+del)*2+0], b1 = band[(kap*3+del)*2+1];
    int si = (int)floorf((b0+1.f)*0.5f*384.f);
    int ei = (int)floorf((b1+1.f)*0.5f*384.f);
    float mix = mixing[0];
    float om  = 1.f - mix;
    const float* cv = g_Cv + (size_t)(b*3+ci)*NPIX + (size_t)n0*N384;
    float* ob = out + (size_t)(co*12 + b*3 + ci)*NPIX + (size_t)n0*N384;

    if (si >= ei) {
        for (int idx = threadIdx.x; idx < 8*N384; idx += blockDim.x) {
            float v = om * cv[idx];
            ob[idx]            = v;
            ob[36*NPIX + idx]  = v;
            ob[72*NPIX + idx]  = v;
            ob[108*NPIX + idx] = v;
        }
        return;
    }

    for (int idx = threadIdx.x; idx < 4*N384; idx += blockDim.x)
        s0[idx] = make_float2(0.f, 0.f);
    __syncthreads();
    const float2* Tm = g_Tmp + (size_t)plane*NPIX;
    int K = ei - si;
    for (int j = threadIdx.x; j < 4*K; j += blockDim.x) {
        int c = j & 3;
        int l = si + (j >> 2);
        float2 T1 = Tm[(size_t)(n0 + 2*c)*N384 + l];
        float2 T2 = Tm[(size_t)(n0 + 2*c + 1)*N384 + l];
        float2 zl = make_float2(T1.x - T2.y, T1.y + T2.x);
        float2 zm = make_float2(T1.x + T2.y, T2.x - T1.y);
        int lm = N384 - l;
        if (lm == l) {
            s0[c*N384 + l] = make_float2(zl.x + zm.x, zl.y + zm.y);
        } else {
            s0[c*N384 + l]  = zl;
            s0[c*N384 + lm] = zm;
        }
    }
    fft384_pre<4>(s0, s1, threadIdx.x, blockDim.x, +1.f);
    const float sc = 1.f/768.f;
    for (int idx = threadIdx.x; idx < 4*192; idx += blockDim.x) {
        int c = idx / 192, q = idx - c*192;
        float2 u = s0[c*N384 + q];
        float2 v = s0[c*N384 + q + 192];
        int n1 = n0 + 2*c;
        #pragma unroll
        for (int half = 0; half < 2; half++) {
            int m = q + half*192;
            float re = (half ? (u.x - v.x) : (u.x + v.x)) * sc;
            float im = (half ? (u.y - v.y) : (u.y + v.y)) * sc;
            float v1 = ((n1 + m) & 1) ? -re : re;
            float v2 = ((n1 + 1 + m) & 1) ? -im : im;
            int i1 = (2*c)*N384 + m, i2 = (2*c+1)*N384 + m;
            float o1 = fmaf(mix, v1, om * cv[i1]);
            float o2 = fmaf(mix, v2, om * cv[i2]);
            ob[i1]            = o1;  ob[i2]            = o2;
            ob[36*NPIX + i1]  = o1;  ob[36*NPIX + i2]  = o2;
            ob[72*NPIX + i1]  = o1;  ob[72*NPIX + i2]  = o2;
            ob[108*NPIX + i1] = o1;  ob[108*NPIX + i2] = o2;
        }
    }
}

// ------ spatial 3x3 conv: 4 pixels x 3 out-channels per thread (float4) ------
__global__ void __launch_bounds__(256)
k_conv(const float* __restrict__ x, const float* __restrict__ cw)
{
    __shared__ float scw[81];
    if (threadIdx.x < 81) scw[threadIdx.x] = cw[threadIdx.x];
    __syncthreads();

    int t = blockIdx.x*256 + threadIdx.x;
    int b = t / (NPIX/4);
    int g = t - b*(NPIX/4);
    int p0 = g*4;
    int h = p0 / N384, w0 = p0 - h*N384;

    float acc[3][4];
    #pragma unroll
    for (int o = 0; o < 3; o++)
        #pragma unroll
        for (int j = 0; j < 4; j++) acc[o][j] = 0.f;

    bool hlo = (h > 0), hhi = (h < 383);
    bool wlo = (w0 > 0), whi = (w0 + 4 < N384);

    #pragma unroll
    for (int i = 0; i < 3; i++) {
        const float* base = x + (size_t)(b*3+i)*NPIX;
        float v[3][6];
        #pragma unroll
        for (int kh = 0; kh < 3; kh++) {
            bool ok = (kh == 0) ? hlo : ((kh == 2) ? hhi : true);
            if (ok) {
                const float* row = base + (h + kh - 1)*N384 + w0;
                v[kh][0] = wlo ? row[-1] : 0.f;
                float4 m = *reinterpret_cast<const float4*>(row);
                v[kh][1] = m.x; v[kh][2] = m.y; v[kh][3] = m.z; v[kh][4] = m.w;
                v[kh][5] = whi ? row[4] : 0.f;
            } else {
                #pragma unroll
                for (int k = 0; k < 6; k++) v[kh][k] = 0.f;
            }
        }
        #pragma unroll
        for (int o = 0; o < 3; o++) {
            const float* wq = scw + (o*3+i)*9;
            #pragma unroll
            for (int kh = 0; kh < 3; kh++)
                #pragma unroll
                for (int kw = 0; kw < 3; kw++) {
                    float wv = wq[kh*3+kw];
                    #pragma unroll
                    for (int j = 0; j < 4; j++)
                        acc[o][j] = fmaf(v[kh][j+kw], wv, acc[o][j]);
                }
        }
    }
    #pragma unroll
    for (int o = 0; o < 3; o++) {
        float4 r = make_float4(acc[o][0], acc[o][1], acc[o][2], acc[o][3]);
        *reinterpret_cast<float4*>(&g_Cv[(size_t)(b*3+o)*NPIX + p0]) = r;
    }
}

// ------------------------------------------------------------------
extern "C" void kernel_launch(void* const* d_in, const int* in_sizes, int n_in,
                              void* d_out, int out_size)
{
    const float* x      = (const float*)d_in[0];
    const float* theta  = (const float*)d_in[1];
    const float* sigma  = (const float*)d_in[2];
    const float* f0     = (const float*)d_in[3];
    const float* theta0 = (const float*)d_in[4];
    const float* aw1    = (const float*)d_in[5];
    const float* ab1    = (const float*)d_in[6];
    const float* aw2    = (const float*)d_in[7];
    const float* ab2    = (const float*)d_in[8];
    const float* convw  = (const float*)d_in[9];
    const float* mixing = (const float*)d_in[10];
    const float* band   = (const float*)d_in[11];
    float* out = (float*)d_out;

    k_fwd_row<<<12*48, 256>>>(x);
    k_fwd_col<<<12*49, 256>>>();
    k_attn<<<(HALF_PIX + 255)/256, 256>>>(theta, sigma, f0, theta0, aw1, ab1, aw2, ab2);
    k_conv<<<4*NPIX/4/256, 256>>>(x, convw);
    k_inv_col<<<36*96, 256>>>(band);
    k_inv_rowout<<<36*48, 256>>>(band, mixing, out);
}